// round 2
// baseline (speedup 1.0000x reference)
#include <cuda_runtime.h>
#include <cuda_bf16.h>

// CBOW hierarchical-softmax loss.
// Inputs (metadata order):
//   d_in[0] context_idxs  int32 [B, C]   B=65536, C=10
//   d_in[1] path_nodes    int32 [B, D]   D=18
//   d_in[2] codes         int32 [B, D]
//   d_in[3] in_embed      f32   [V, E]   V=100000, E=128
//   d_in[4] node_embed    f32   [N, E]   N=99999
// Output: loss f32 [B]
//
// One warp per example; lane owns 4 columns (float4) of the E=128 row.
// R2: int2-vectorized index loads (46->23 LDGs/warp), chunked D loop (3x6)
//     to cut live registers, occupancy forced to 48 warps/SM.

#define B_ 65536
#define C_ 10
#define D_ 18
#define E_ 128
#define EPS_ 1e-9f

__device__ __forceinline__ float dot4(float4 a, float4 b) {
    return fmaf(a.x, b.x, fmaf(a.y, b.y, fmaf(a.z, b.z, a.w * b.w)));
}

__global__ void __launch_bounds__(256, 6) cbow_hs_kernel(
    const int* __restrict__ ctx,
    const int* __restrict__ path,
    const int* __restrict__ codes,
    const float* __restrict__ in_emb,
    const float* __restrict__ node_emb,
    float* __restrict__ out)
{
    const int warp = (blockIdx.x * blockDim.x + threadIdx.x) >> 5;
    const int lane = threadIdx.x & 31;
    if (warp >= B_) return;

    const float4* __restrict__ in4 = reinterpret_cast<const float4*>(in_emb);
    const float4* __restrict__ nd4 = reinterpret_cast<const float4*>(node_emb);

    // ---- context indices: 5 x int2 (rows are 40B, 8B-aligned) ----
    const int2* __restrict__ ctx2 = reinterpret_cast<const int2*>(ctx + warp * C_);
    int cidx[C_];
#pragma unroll
    for (int j = 0; j < C_ / 2; j++) {
        int2 c = __ldg(&ctx2[j]);
        cidx[2 * j] = c.x;
        cidx[2 * j + 1] = c.y;
    }

    // ---- context mean: v (10 independent 512B row gathers) ----
    float4 v = make_float4(0.f, 0.f, 0.f, 0.f);
#pragma unroll
    for (int j = 0; j < C_; j++) {
        float4 e = __ldg(&in4[(long)cidx[j] * (E_ / 4) + lane]);
        v.x += e.x; v.y += e.y; v.z += e.z; v.w += e.w;
    }
    const float inv = 1.0f / (float)C_;
    v.x *= inv; v.y *= inv; v.z *= inv; v.w *= inv;

    // ---- path: 3 chunks of 6 nodes ----
    const int2* __restrict__ pn2 = reinterpret_cast<const int2*>(path + warp * D_);
    const int2* __restrict__ cd2 = reinterpret_cast<const int2*>(codes + warp * D_);

    float loss = 0.f;
#pragma unroll
    for (int t = 0; t < 3; t++) {
        // 3 int2 index loads + 3 int2 code loads per chunk
        int pn[6], cd[6];
#pragma unroll
        for (int j = 0; j < 3; j++) {
            int2 p = __ldg(&pn2[t * 3 + j]);
            int2 q = __ldg(&cd2[t * 3 + j]);
            pn[2 * j] = p.x; pn[2 * j + 1] = p.y;
            cd[2 * j] = q.x; cd[2 * j + 1] = q.y;
        }

        // 6 independent row gathers -> 6 per-lane partial dots
        float part[6];
#pragma unroll
        for (int d = 0; d < 6; d++) {
            float4 u = __ldg(&nd4[(long)pn[d] * (E_ / 4) + lane]);
            part[d] = dot4(u, v);
        }

        // butterfly-reduce the 6 partials, accumulate loss
#pragma unroll
        for (int d = 0; d < 6; d++) {
            float s = part[d];
#pragma unroll
            for (int o = 16; o > 0; o >>= 1)
                s += __shfl_xor_sync(0xFFFFFFFFu, s, o);
            float x = cd[d] ? s : -s;   // p = sigmoid(x) if code==1 else sigmoid(-x)
            float sig = __fdividef(1.0f, 1.0f + __expf(-x));
            loss += __logf(sig + EPS_);
        }
    }

    if (lane == 0)
        out[warp] = -loss;
}

extern "C" void kernel_launch(void* const* d_in, const int* in_sizes, int n_in,
                              void* d_out, int out_size)
{
    const int*   ctx      = (const int*)d_in[0];
    const int*   path     = (const int*)d_in[1];
    const int*   codes    = (const int*)d_in[2];
    const float* in_emb   = (const float*)d_in[3];
    const float* node_emb = (const float*)d_in[4];
    float*       out      = (float*)d_out;

    const int threads = 256;               // 8 warps/block
    const int total   = B_ * 32;
    const int blocks  = (total + threads - 1) / threads;
    cbow_hs_kernel<<<blocks, threads>>>(ctx, path, codes, in_emb, node_emb, out);
}

// round 4
// speedup vs baseline: 1.1423x; 1.1423x over previous
#include <cuda_runtime.h>
#include <cuda_bf16.h>

// CBOW hierarchical-softmax loss.
// Inputs (metadata order):
//   d_in[0] context_idxs  int32 [B, C]   B=65536, C=10
//   d_in[1] path_nodes    int32 [B, D]   D=18
//   d_in[2] codes         int32 [B, D]
//   d_in[3] in_embed      f32   [V, E]   V=100000, E=128
//   d_in[4] node_embed    f32   [N, E]   N=99999
// Output: loss f32 [B]
//
// One warp per example; lane owns 4 columns of the E=128 row (one 16B load).
// R4: flat MLP=18 gathers (R1 shape) + packed f32x2 math + pair-packed
//     f32x2 butterfly reduction (135 instr vs 180) + epilogue distributed
//     across lanes (3 MUFU/warp instead of 54).

#define B_ 65536
#define C_ 10
#define D_ 18
#define E_ 128
#define EPS_ 1e-9f

typedef unsigned long long u64;

__device__ __forceinline__ u64 f32x2_add(u64 a, u64 b) {
    u64 r; asm("add.rn.f32x2 %0, %1, %2;" : "=l"(r) : "l"(a), "l"(b)); return r;
}
__device__ __forceinline__ u64 f32x2_mul(u64 a, u64 b) {
    u64 r; asm("mul.rn.f32x2 %0, %1, %2;" : "=l"(r) : "l"(a), "l"(b)); return r;
}
__device__ __forceinline__ u64 f32x2_fma(u64 a, u64 b, u64 c) {
    u64 r; asm("fma.rn.f32x2 %0, %1, %2, %3;" : "=l"(r) : "l"(a), "l"(b), "l"(c)); return r;
}
__device__ __forceinline__ u64 pack2(float lo, float hi) {
    u64 r; asm("mov.b64 %0, {%1, %2};" : "=l"(r) : "f"(lo), "f"(hi)); return r;
}
__device__ __forceinline__ float2 unpack2(u64 v) {
    float2 f; asm("mov.b64 {%0, %1}, %2;" : "=f"(f.x), "=f"(f.y) : "l"(v)); return f;
}
__device__ __forceinline__ u64 shfl_xor_u64(u64 v, int o) {
    uint2 t; asm("mov.b64 {%0, %1}, %2;" : "=r"(t.x), "=r"(t.y) : "l"(v));
    t.x = __shfl_xor_sync(0xFFFFFFFFu, t.x, o);
    t.y = __shfl_xor_sync(0xFFFFFFFFu, t.y, o);
    u64 r; asm("mov.b64 %0, {%1, %2};" : "=l"(r) : "r"(t.x), "r"(t.y));
    return r;
}

__global__ void __launch_bounds__(256) cbow_hs_kernel(
    const int* __restrict__ ctx,
    const int* __restrict__ path,
    const int* __restrict__ codes,
    const float* __restrict__ in_emb,
    const float* __restrict__ node_emb,
    float* __restrict__ out)
{
    const int warp = (blockIdx.x * blockDim.x + threadIdx.x) >> 5;
    const int lane = threadIdx.x & 31;
    if (warp >= B_) return;

    // Rows viewed as ulonglong2: 128 f32 = 32 x 16B per row; lane owns one.
    const ulonglong2* __restrict__ in2 = reinterpret_cast<const ulonglong2*>(in_emb);
    const ulonglong2* __restrict__ nd2 = reinterpret_cast<const ulonglong2*>(node_emb);

    // ---- per-lane code: one coalesced 72B LDG per warp ----
    int code_l = 0;
    if (lane < D_) code_l = __ldg(&codes[warp * D_ + lane]);

    // ---- context indices: 5 x int2 (rows 40B, 8B-aligned) ----
    const int2* __restrict__ ctx2 = reinterpret_cast<const int2*>(ctx + warp * C_);
    int cidx[C_];
#pragma unroll
    for (int j = 0; j < C_ / 2; j++) {
        int2 c = __ldg(&ctx2[j]);
        cidx[2 * j]     = c.x;
        cidx[2 * j + 1] = c.y;
    }

    // ---- context mean: v (10 independent 512B row gathers, packed adds) ----
    u64 v01 = 0ull, v23 = 0ull;
#pragma unroll
    for (int j = 0; j < C_; j++) {
        ulonglong2 e = __ldg(&in2[(size_t)cidx[j] * (E_ / 4) + lane]);
        v01 = f32x2_add(v01, e.x);
        v23 = f32x2_add(v23, e.y);
    }
    const u64 inv = pack2(1.0f / (float)C_, 1.0f / (float)C_);
    v01 = f32x2_mul(v01, inv);
    v23 = f32x2_mul(v23, inv);

    // ---- path indices: 9 x int2 (rows 72B, 8B-aligned) ----
    const int2* __restrict__ pn2 = reinterpret_cast<const int2*>(path + warp * D_);
    int pn[D_];
#pragma unroll
    for (int j = 0; j < D_ / 2; j++) {
        int2 p = __ldg(&pn2[j]);
        pn[2 * j] = p.x; pn[2 * j + 1] = p.y;
    }

    // ---- 18 independent node-row gathers -> 9 packed per-lane partials ----
    u64 pair[D_ / 2];
#pragma unroll
    for (int j = 0; j < D_ / 2; j++) {
        ulonglong2 u0 = __ldg(&nd2[(size_t)pn[2 * j]     * (E_ / 4) + lane]);
        ulonglong2 u1 = __ldg(&nd2[(size_t)pn[2 * j + 1] * (E_ / 4) + lane]);
        u64 m0 = f32x2_fma(u0.y, v23, f32x2_mul(u0.x, v01));
        u64 m1 = f32x2_fma(u1.y, v23, f32x2_mul(u1.x, v01));
        float2 f0 = unpack2(m0);
        float2 f1 = unpack2(m1);
        pair[j] = pack2(f0.x + f0.y, f1.x + f1.y);
    }

    // ---- pair-packed butterfly: 9 u64 reduced across lanes in 5 steps ----
#pragma unroll
    for (int o = 16; o > 0; o >>= 1) {
#pragma unroll
        for (int j = 0; j < D_ / 2; j++)
            pair[j] = f32x2_add(pair[j], shfl_xor_u64(pair[j], o));
    }

    // ---- capture this lane's logit: lane d takes s_d ----
    const int mypair_idx = lane >> 1;
    u64 mypair = pair[0];
#pragma unroll
    for (int j = 1; j < D_ / 2; j++)
        mypair = (j == mypair_idx) ? pair[j] : mypair;
    float2 sp = unpack2(mypair);
    float s = (lane & 1) ? sp.y : sp.x;

    // ---- epilogue once per warp (3 MUFU instead of 54) ----
    float x = code_l ? s : -s;   // p = sigmoid(x) if code==1 else sigmoid(-x)
    float sig = __fdividef(1.0f, 1.0f + __expf(-x));
    float term = __logf(sig + EPS_);
    term = (lane < D_) ? term : 0.f;

    // ---- sum the 18 log terms across lanes ----
#pragma unroll
    for (int o = 16; o > 0; o >>= 1)
        term += __shfl_xor_sync(0xFFFFFFFFu, term, o);

    if (lane == 0)
        out[warp] = -term;
}

extern "C" void kernel_launch(void* const* d_in, const int* in_sizes, int n_in,
                              void* d_out, int out_size)
{
    const int*   ctx      = (const int*)d_in[0];
    const int*   path     = (const int*)d_in[1];
    const int*   codes    = (const int*)d_in[2];
    const float* in_emb   = (const float*)d_in[3];
    const float* node_emb = (const float*)d_in[4];
    float*       out      = (float*)d_out;

    const int threads = 256;               // 8 warps/block
    const int total   = B_ * 32;
    const int blocks  = (total + threads - 1) / threads;
    cbow_hs_kernel<<<blocks, threads>>>(ctx, path, codes, in_emb, node_emb, out);
}